// round 2
// baseline (speedup 1.0000x reference)
#include <cuda_runtime.h>
#include <math.h>

#define NN   2048
#define TT   5
#define DD   64
#define KK   21
#define BB   32
#define ROWS (BB*NN)
#define RED_BLOCKS 128

// ---- scratch (device globals; no runtime allocation) ----
__device__ float g_cos[NN*NN];      // 16 MB
__device__ float g_norm[NN];
__device__ int   g_idx[NN*KK];
__device__ float g_h[ROWS*DD];      // 16 MB
__device__ float g_esrc[ROWS];
__device__ float g_edst[ROWS];
__device__ float g_obuf[ROWS*DD];   // 16 MB
__device__ float g_part[RED_BLOCKS*128];  // per block: 64 sums + 64 sumsqs
__device__ float g_mean[DD];
__device__ float g_inv[DD];

// ---------------------------------------------------------------------------
// 1) row norms of emb
__global__ void norm_kernel(const float* __restrict__ emb) {
    int r = blockIdx.x * blockDim.x + threadIdx.x;
    if (r < NN) {
        const float4* p = (const float4*)(emb + r * DD);
        float s = 0.f;
        #pragma unroll
        for (int u = 0; u < DD/4; u++) {
            float4 v = p[u];
            s += v.x*v.x + v.y*v.y + v.z*v.z + v.w*v.w;
        }
        g_norm[r] = sqrtf(s);
    }
}

// ---------------------------------------------------------------------------
// 2) cos = (emb @ emb^T) / (norm_i * norm_j)    64x64 tile, 4x4 per thread
__global__ __launch_bounds__(256) void cos_kernel(const float* __restrict__ emb) {
    __shared__ float As[DD][64];   // [k][row]
    __shared__ float Bs[DD][64];
    int bi = blockIdx.y * 64;
    int bj = blockIdx.x * 64;
    int tx = threadIdx.x, ty = threadIdx.y;     // 16x16
    int t  = ty * 16 + tx;

    #pragma unroll
    for (int u = 0; u < 4; u++) {
        int idx = t + u * 256;            // 0..1023
        int row = idx >> 4;               // 0..63
        int c4  = idx & 15;               // float4 index
        float4 a = *(const float4*)(emb + (bi + row) * DD + c4 * 4);
        As[c4*4+0][row] = a.x; As[c4*4+1][row] = a.y;
        As[c4*4+2][row] = a.z; As[c4*4+3][row] = a.w;
        float4 b = *(const float4*)(emb + (bj + row) * DD + c4 * 4);
        Bs[c4*4+0][row] = b.x; Bs[c4*4+1][row] = b.y;
        Bs[c4*4+2][row] = b.z; Bs[c4*4+3][row] = b.w;
    }
    __syncthreads();

    float acc[4][4];
    #pragma unroll
    for (int u = 0; u < 4; u++)
        #pragma unroll
        for (int v = 0; v < 4; v++) acc[u][v] = 0.f;

    #pragma unroll
    for (int k = 0; k < DD; k++) {
        float4 a = *(const float4*)&As[k][ty * 4];
        float4 b = *(const float4*)&Bs[k][tx * 4];
        float ar[4] = {a.x, a.y, a.z, a.w};
        float br[4] = {b.x, b.y, b.z, b.w};
        #pragma unroll
        for (int u = 0; u < 4; u++)
            #pragma unroll
            for (int v = 0; v < 4; v++) acc[u][v] += ar[u] * br[v];
    }

    float ni[4], nj[4];
    #pragma unroll
    for (int u = 0; u < 4; u++) ni[u] = g_norm[bi + ty*4 + u];
    #pragma unroll
    for (int v = 0; v < 4; v++) nj[v] = g_norm[bj + tx*4 + v];

    #pragma unroll
    for (int u = 0; u < 4; u++) {
        int i = bi + ty*4 + u;
        #pragma unroll
        for (int v = 0; v < 4; v++) {
            int j = bj + tx*4 + v;
            g_cos[(long)i * NN + j] = acc[u][v] / (ni[u] * nj[v]);
        }
    }
}

// ---------------------------------------------------------------------------
// 3) top-21 per row (iterative argmax, lower-index tie-break like jax top_k)
__global__ __launch_bounds__(256) void topk_kernel() {
    __shared__ float sv[NN];
    __shared__ float rv[8];
    __shared__ int   ri[8];
    int i = blockIdx.x;
    int t = threadIdx.x;
    const float4* row = (const float4*)(g_cos + (long)i * NN);
    #pragma unroll
    for (int u = 0; u < 2; u++) {
        float4 v = row[t + u * 256];
        int base = (t + u * 256) * 4;
        sv[base+0] = v.x; sv[base+1] = v.y; sv[base+2] = v.z; sv[base+3] = v.w;
    }
    __syncthreads();

    int lane = t & 31, warp = t >> 5;
    for (int k = 0; k < KK; k++) {
        float bestv = -3e38f; int besti = 0;
        #pragma unroll
        for (int u = 0; u < 8; u++) {
            int j = t + u * 256;
            float v = sv[j];
            if (v > bestv) { bestv = v; besti = j; }
        }
        #pragma unroll
        for (int off = 16; off; off >>= 1) {
            float ov = __shfl_down_sync(0xffffffffu, bestv, off);
            int   oi = __shfl_down_sync(0xffffffffu, besti, off);
            if (ov > bestv || (ov == bestv && oi < besti)) { bestv = ov; besti = oi; }
        }
        if (lane == 0) { rv[warp] = bestv; ri[warp] = besti; }
        __syncthreads();
        if (t == 0) {
            float bv = rv[0]; int bi2 = ri[0];
            #pragma unroll
            for (int w = 1; w < 8; w++) {
                if (rv[w] > bv || (rv[w] == bv && ri[w] < bi2)) { bv = rv[w]; bi2 = ri[w]; }
            }
            g_idx[i * KK + k] = bi2;
            sv[bi2] = -3e38f;
        }
        __syncthreads();
    }
}

// ---------------------------------------------------------------------------
// 4) h = x @ W^T + Wb ; e_src/e_dst = [h, emb] . a_{src,dst}   (warp per row)
__global__ __launch_bounds__(256) void h_kernel(
    const float* __restrict__ x, const float* __restrict__ emb,
    const float* __restrict__ W, const float* __restrict__ Wb,
    const float* __restrict__ a_src, const float* __restrict__ a_dst) {
    __shared__ float sW[DD * TT];
    int t = threadIdx.x;
    for (int q = t; q < DD * TT; q += 256) sW[q] = W[q];
    __syncthreads();

    int warp = t >> 5, lane = t & 31;
    int row = blockIdx.x * 8 + warp;            // < ROWS
    int n = row & (NN - 1);
    const float* xp = x + (long)row * TT;
    float xv[TT];
    #pragma unroll
    for (int tt = 0; tt < TT; tt++) xv[tt] = xp[tt];

    int c0 = lane, c1 = lane + 32;
    float h0 = Wb[c0], h1 = Wb[c1];
    #pragma unroll
    for (int tt = 0; tt < TT; tt++) {
        h0 += xv[tt] * sW[c0 * TT + tt];
        h1 += xv[tt] * sW[c1 * TT + tt];
    }
    g_h[(long)row * DD + c0] = h0;
    g_h[(long)row * DD + c1] = h1;

    float e0 = emb[n * DD + c0], e1 = emb[n * DD + c1];
    float ps = h0 * a_src[c0] + h1 * a_src[c1] + e0 * a_src[DD + c0] + e1 * a_src[DD + c1];
    float pd = h0 * a_dst[c0] + h1 * a_dst[c1] + e0 * a_dst[DD + c0] + e1 * a_dst[DD + c1];
    #pragma unroll
    for (int off = 16; off; off >>= 1) {
        ps += __shfl_down_sync(0xffffffffu, ps, off);
        pd += __shfl_down_sync(0xffffffffu, pd, off);
    }
    if (lane == 0) { g_esrc[row] = ps; g_edst[row] = pd; }
}

// ---------------------------------------------------------------------------
// 5) sparse attention: leaky-relu, softmax over 21 nbrs, z=relu(alpha@h), o=z*emb
__global__ __launch_bounds__(256) void agg_kernel(const float* __restrict__ emb) {
    int t = threadIdx.x, warp = t >> 5, lane = t & 31;
    int row = blockIdx.x * 8 + warp;
    int b = row >> 11;
    int i = row & (NN - 1);

    float es = g_esrc[row];
    float e = -3e38f; int j = 0;
    if (lane < KK) {
        j = g_idx[i * KK + lane];
        float v = es + g_edst[b * NN + j];
        e = (v > 0.f) ? v : 0.2f * v;        // leaky_relu(0.2)
    }
    float m = e;
    #pragma unroll
    for (int off = 16; off; off >>= 1)
        m = fmaxf(m, __shfl_xor_sync(0xffffffffu, m, off));
    float w = (lane < KK) ? __expf(e - m) : 0.f;
    float s = w;
    #pragma unroll
    for (int off = 16; off; off >>= 1)
        s += __shfl_xor_sync(0xffffffffu, s, off);

    float z0 = 0.f, z1 = 0.f;
    #pragma unroll
    for (int k = 0; k < KK; k++) {
        float wk = __shfl_sync(0xffffffffu, w, k);
        int   jk = __shfl_sync(0xffffffffu, j, k);
        const float* hp = g_h + (long)(b * NN + jk) * DD;
        z0 += wk * hp[lane];
        z1 += wk * hp[lane + 32];
    }
    float rs = 1.f / s;
    z0 = fmaxf(z0 * rs, 0.f);
    z1 = fmaxf(z1 * rs, 0.f);
    const float* ep = emb + i * DD;
    g_obuf[(long)row * DD + lane]      = z0 * ep[lane];
    g_obuf[(long)row * DD + lane + 32] = z1 * ep[lane + 32];
}

// ---------------------------------------------------------------------------
// 6) BN stats partial reduce (deterministic, no atomics)
__global__ __launch_bounds__(256) void red_kernel() {
    __shared__ float ss[256], sq[256];
    int gt = blockIdx.x * 256 + threadIdx.x;   // RED_BLOCKS*256 = 32768 threads
    const int stride = RED_BLOCKS * 256;       // multiple of 64 -> fixed channel
    float s = 0.f, s2 = 0.f;
    for (long idx = gt; idx < (long)ROWS * DD; idx += stride) {
        float v = g_obuf[idx];
        s += v; s2 += v * v;
    }
    ss[threadIdx.x] = s; sq[threadIdx.x] = s2;
    __syncthreads();
    if (threadIdx.x < 64) {
        float a  = ss[threadIdx.x] + ss[threadIdx.x + 64] + ss[threadIdx.x + 128] + ss[threadIdx.x + 192];
        float b2 = sq[threadIdx.x] + sq[threadIdx.x + 64] + sq[threadIdx.x + 128] + sq[threadIdx.x + 192];
        g_part[blockIdx.x * 128 + threadIdx.x]      = a;
        g_part[blockIdx.x * 128 + 64 + threadIdx.x] = b2;
    }
}

// 7) finalize mean / rsqrt(var+eps)
__global__ void stats_kernel() {
    int c = threadIdx.x;  // 64
    float s = 0.f, s2 = 0.f;
    for (int bk = 0; bk < RED_BLOCKS; bk++) {
        s  += g_part[bk * 128 + c];
        s2 += g_part[bk * 128 + 64 + c];
    }
    float mean = s / (float)ROWS;
    float var  = s2 / (float)ROWS - mean * mean;
    g_mean[c] = mean;
    g_inv[c]  = rsqrtf(var + 1e-5f);
}

// ---------------------------------------------------------------------------
// 8) BN apply + relu + fc  (warp per row)
__global__ __launch_bounds__(256) void out_kernel(
    const float* __restrict__ gamma, const float* __restrict__ beta,
    const float* __restrict__ fcw, const float* __restrict__ fcb,
    float* __restrict__ out) {
    int t = threadIdx.x, warp = t >> 5, lane = t & 31;
    int row = blockIdx.x * 8 + warp;
    int c0 = lane, c1 = lane + 32;
    float o0 = g_obuf[(long)row * DD + c0];
    float o1 = g_obuf[(long)row * DD + c1];
    float v0 = fmaxf((o0 - g_mean[c0]) * g_inv[c0] * gamma[c0] + beta[c0], 0.f) * fcw[c0];
    float v1 = fmaxf((o1 - g_mean[c1]) * g_inv[c1] * gamma[c1] + beta[c1], 0.f) * fcw[c1];
    float acc = v0 + v1;
    #pragma unroll
    for (int off = 16; off; off >>= 1)
        acc += __shfl_down_sync(0xffffffffu, acc, off);
    if (lane == 0) out[row] = acc + fcb[0];
}

// ---------------------------------------------------------------------------
extern "C" void kernel_launch(void* const* d_in, const int* in_sizes, int n_in,
                              void* d_out, int out_size) {
    const float* x     = (const float*)d_in[0];
    const float* emb   = (const float*)d_in[1];
    const float* W     = (const float*)d_in[2];
    const float* Wb    = (const float*)d_in[3];
    const float* a_src = (const float*)d_in[4];
    const float* a_dst = (const float*)d_in[5];
    const float* gamma = (const float*)d_in[6];
    const float* beta  = (const float*)d_in[7];
    const float* fcw   = (const float*)d_in[8];
    const float* fcb   = (const float*)d_in[9];
    float* out = (float*)d_out;

    norm_kernel<<<(NN + 255) / 256, 256>>>(emb);
    cos_kernel<<<dim3(NN/64, NN/64), dim3(16, 16)>>>(emb);
    topk_kernel<<<NN, 256>>>();
    h_kernel<<<ROWS/8, 256>>>(x, emb, W, Wb, a_src, a_dst);
    agg_kernel<<<ROWS/8, 256>>>(emb);
    red_kernel<<<RED_BLOCKS, 256>>>();
    stats_kernel<<<1, 64>>>();
    out_kernel<<<ROWS/8, 256>>>(gamma, beta, fcw, fcb, out);
}

// round 5
// speedup vs baseline: 1.2611x; 1.2611x over previous
#include <cuda_runtime.h>
#include <math.h>

#define NN   2048
#define TT   5
#define DD   64
#define KK   21
#define BB   32
#define ROWS (BB*NN)
#define RED_BLOCKS 128

// ---- scratch (device globals; no runtime allocation) ----
__device__ float g_cos[NN*NN];      // 16 MB
__device__ float g_norm[NN];
__device__ float g_ces[NN];         // emb . a_src[64:]
__device__ float g_ced[NN];         // emb . a_dst[64:]
__device__ float g_ws[TT];          // W^T a_src[:64]
__device__ float g_wd[TT];
__device__ float g_bs[2];           // Wb.a_src[:64], Wb.a_dst[:64]
__device__ int   g_idx[NN*KK];
__device__ float g_h[ROWS*DD];      // 16 MB
__device__ float g_esrc[ROWS];
__device__ float g_edst[ROWS];
__device__ float g_obuf[ROWS*DD];   // 16 MB
__device__ float g_part[RED_BLOCKS*128];
__device__ float g_mean[DD];
__device__ float g_inv[DD];

// monotonic float->uint key (total order matches float >)
__device__ __forceinline__ unsigned fkey(float f) {
    unsigned b = __float_as_uint(f);
    return (b & 0x80000000u) ? ~b : (b | 0x80000000u);
}

// ---------------------------------------------------------------------------
// 1) pre: per-node norms + emb-attention constants; warp 0 of block 0 also
//    computes the 5-dim projected attention weights.
__global__ __launch_bounds__(256) void pre_kernel(
    const float* __restrict__ emb, const float* __restrict__ W,
    const float* __restrict__ Wb,
    const float* __restrict__ a_src, const float* __restrict__ a_dst) {
    int t = threadIdx.x, lane = t & 31, w = t >> 5;
    int n = blockIdx.x * 8 + w;

    float e0 = emb[n * DD + lane], e1 = emb[n * DD + lane + 32];
    float s  = e0 * e0 + e1 * e1;
    float ps = e0 * a_src[DD + lane] + e1 * a_src[DD + lane + 32];
    float pd = e0 * a_dst[DD + lane] + e1 * a_dst[DD + lane + 32];
    #pragma unroll
    for (int off = 16; off; off >>= 1) {
        s  += __shfl_down_sync(0xffffffffu, s, off);
        ps += __shfl_down_sync(0xffffffffu, ps, off);
        pd += __shfl_down_sync(0xffffffffu, pd, off);
    }
    if (lane == 0) {
        g_norm[n] = sqrtf(s);
        g_ces[n] = ps;
        g_ced[n] = pd;
    }

    if (blockIdx.x == 0 && w == 0) {
        float a0 = a_src[lane], a1 = a_src[lane + 32];
        float d0 = a_dst[lane], d1 = a_dst[lane + 32];
        #pragma unroll
        for (int tt = 0; tt < TT; tt++) {
            float w0 = W[lane * TT + tt], w1 = W[(lane + 32) * TT + tt];
            float vs = w0 * a0 + w1 * a1;
            float vd = w0 * d0 + w1 * d1;
            #pragma unroll
            for (int off = 16; off; off >>= 1) {
                vs += __shfl_down_sync(0xffffffffu, vs, off);
                vd += __shfl_down_sync(0xffffffffu, vd, off);
            }
            if (lane == 0) { g_ws[tt] = vs; g_wd[tt] = vd; }
        }
        float b0 = Wb[lane], b1 = Wb[lane + 32];
        float vbs = b0 * a0 + b1 * a1;
        float vbd = b0 * d0 + b1 * d1;
        #pragma unroll
        for (int off = 16; off; off >>= 1) {
            vbs += __shfl_down_sync(0xffffffffu, vbs, off);
            vbd += __shfl_down_sync(0xffffffffu, vbd, off);
        }
        if (lane == 0) { g_bs[0] = vbs; g_bs[1] = vbd; }
    }
}

// ---------------------------------------------------------------------------
// 2) cos = (emb @ emb^T) / (norm_i * norm_j)    64x64 tile, 4x4 per thread
__global__ __launch_bounds__(256) void cos_kernel(const float* __restrict__ emb) {
    __shared__ float As[DD][64];
    __shared__ float Bs[DD][64];
    int bi = blockIdx.y * 64;
    int bj = blockIdx.x * 64;
    int tx = threadIdx.x, ty = threadIdx.y;
    int t  = ty * 16 + tx;

    #pragma unroll
    for (int u = 0; u < 4; u++) {
        int idx = t + u * 256;
        int row = idx >> 4;
        int c4  = idx & 15;
        float4 a = *(const float4*)(emb + (bi + row) * DD + c4 * 4);
        As[c4*4+0][row] = a.x; As[c4*4+1][row] = a.y;
        As[c4*4+2][row] = a.z; As[c4*4+3][row] = a.w;
        float4 b = *(const float4*)(emb + (bj + row) * DD + c4 * 4);
        Bs[c4*4+0][row] = b.x; Bs[c4*4+1][row] = b.y;
        Bs[c4*4+2][row] = b.z; Bs[c4*4+3][row] = b.w;
    }
    __syncthreads();

    float acc[4][4];
    #pragma unroll
    for (int u = 0; u < 4; u++)
        #pragma unroll
        for (int v = 0; v < 4; v++) acc[u][v] = 0.f;

    #pragma unroll
    for (int k = 0; k < DD; k++) {
        float4 a = *(const float4*)&As[k][ty * 4];
        float4 b = *(const float4*)&Bs[k][tx * 4];
        float ar[4] = {a.x, a.y, a.z, a.w};
        float br[4] = {b.x, b.y, b.z, b.w};
        #pragma unroll
        for (int u = 0; u < 4; u++)
            #pragma unroll
            for (int v = 0; v < 4; v++) acc[u][v] += ar[u] * br[v];
    }

    float ni[4], nj[4];
    #pragma unroll
    for (int u = 0; u < 4; u++) ni[u] = g_norm[bi + ty*4 + u];
    #pragma unroll
    for (int v = 0; v < 4; v++) nj[v] = g_norm[bj + tx*4 + v];

    #pragma unroll
    for (int u = 0; u < 4; u++) {
        int i = bi + ty*4 + u;
        #pragma unroll
        for (int v = 0; v < 4; v++) {
            int j = bj + tx*4 + v;
            g_cos[(size_t)i * NN + j] = acc[u][v] / (ni[u] * nj[v]);
        }
    }
}

// ---------------------------------------------------------------------------
// 3) top-21: per-warp register-resident iterative argmax (redux-based),
//    then warp 0 merges 8x21 candidates. Tie-break: lower index first.
__global__ __launch_bounds__(256) void topk_kernel() {
    __shared__ unsigned cvs[8 * KK];
    __shared__ int      cis[8 * KK];
    int i = blockIdx.x;
    int t = threadIdx.x, lane = t & 31, w = t >> 5;

    // lane holds 8 contiguous values: indices base..base+7
    int base = w * 256 + lane * 8;
    const float4* row4 = (const float4*)(g_cos + (size_t)i * NN);
    float4 aa = row4[(base >> 2)];
    float4 bb = row4[(base >> 2) + 1];
    float v[8] = {aa.x, aa.y, aa.z, aa.w, bb.x, bb.y, bb.z, bb.w};

    #pragma unroll 1
    for (int k = 0; k < KK; k++) {
        float bv = v[0]; int bq = 0;
        #pragma unroll
        for (int q = 1; q < 8; q++) if (v[q] > bv) { bv = v[q]; bq = q; }
        int bidx = base + bq;
        unsigned bk = fkey(bv);
        unsigned mk = __reduce_max_sync(0xffffffffu, bk);
        int cand = (bk == mk) ? bidx : 0x7fffffff;
        int widx = __reduce_min_sync(0xffffffffu, cand);
        if (lane == 0) { cvs[w * KK + k] = mk; cis[w * KK + k] = widx; }
        #pragma unroll
        for (int q = 0; q < 8; q++) if (widx == base + q) v[q] = -3e38f;
    }
    __syncthreads();

    if (w == 0) {
        unsigned kv[6]; int ki[6];
        #pragma unroll
        for (int q = 0; q < 6; q++) {
            int s = lane + 32 * q;
            if (s < 8 * KK) { kv[q] = cvs[s]; ki[q] = cis[s]; }
            else            { kv[q] = 0u;     ki[q] = 0x7fffffff; }
        }
        #pragma unroll 1
        for (int k = 0; k < KK; k++) {
            unsigned bkk = kv[0]; int bii = ki[0];
            #pragma unroll
            for (int q = 1; q < 6; q++) {
                if (kv[q] > bkk || (kv[q] == bkk && ki[q] < bii)) { bkk = kv[q]; bii = ki[q]; }
            }
            unsigned mk = __reduce_max_sync(0xffffffffu, bkk);
            int cand = (bkk == mk) ? bii : 0x7fffffff;
            int widx = __reduce_min_sync(0xffffffffu, cand);
            if (lane == 0) g_idx[i * KK + k] = widx;
            #pragma unroll
            for (int q = 0; q < 6; q++) if (ki[q] == widx) kv[q] = 0u;
        }
    }
}

// ---------------------------------------------------------------------------
// 4) h = x @ W^T + Wb (streamed), e_src/e_dst via 5-dim dots + per-node consts
__global__ __launch_bounds__(256) void h2_kernel(
    const float* __restrict__ x, const float* __restrict__ W,
    const float* __restrict__ Wb) {
    __shared__ float sW[DD * TT];
    __shared__ float sWb[DD];
    __shared__ float sx[32 * TT];
    int t = threadIdx.x;
    for (int q = t; q < DD * TT; q += 256) sW[q] = W[q];   // 320 elems: 2 rounds
    if (t < DD) sWb[t] = Wb[t];
    if (t < 32 * TT) sx[t] = x[blockIdx.x * 32 * TT + t];
    __syncthreads();

    int rl = t >> 3;                 // local row 0..31
    int cg = (t & 7) * 8;            // channel group
    int row = blockIdx.x * 32 + rl;

    float xv[TT];
    #pragma unroll
    for (int tt = 0; tt < TT; tt++) xv[tt] = sx[rl * TT + tt];

    float h[8];
    #pragma unroll
    for (int j = 0; j < 8; j++) {
        int c = cg + j;
        float acc = sWb[c];
        #pragma unroll
        for (int tt = 0; tt < TT; tt++) acc += xv[tt] * sW[c * TT + tt];
        h[j] = acc;
    }
    float4* hp = (float4*)(g_h + ((size_t)row << 6) + cg);
    hp[0] = make_float4(h[0], h[1], h[2], h[3]);
    hp[1] = make_float4(h[4], h[5], h[6], h[7]);

    if ((t & 7) == 0) {
        int n = row & (NN - 1);
        float es = g_bs[0], ed = g_bs[1];
        #pragma unroll
        for (int tt = 0; tt < TT; tt++) {
            es += xv[tt] * g_ws[tt];
            ed += xv[tt] * g_wd[tt];
        }
        g_esrc[row] = es + g_ces[n];
        g_edst[row] = ed + g_ced[n];
    }
}

// ---------------------------------------------------------------------------
// 5) sparse attention + z*emb (channels 2*lane, 2*lane+1; float2 gathers)
__global__ __launch_bounds__(256) void agg_kernel(const float* __restrict__ emb) {
    int t = threadIdx.x, w = t >> 5, lane = t & 31;
    int row = blockIdx.x * 8 + w;
    int b = row >> 11;
    int i = row & (NN - 1);

    float es = g_esrc[row];
    float e = -3e38f; int j = 0;
    if (lane < KK) {
        j = g_idx[i * KK + lane];
        float v = es + g_edst[(b << 11) + j];
        e = (v > 0.f) ? v : 0.2f * v;
    }
    float m = e;
    #pragma unroll
    for (int off = 16; off; off >>= 1)
        m = fmaxf(m, __shfl_xor_sync(0xffffffffu, m, off));
    float wgt = (lane < KK) ? __expf(e - m) : 0.f;
    float s = wgt;
    #pragma unroll
    for (int off = 16; off; off >>= 1)
        s += __shfl_xor_sync(0xffffffffu, s, off);

    float z0 = 0.f, z1 = 0.f;
    #pragma unroll
    for (int k = 0; k < KK; k++) {
        float wk = __shfl_sync(0xffffffffu, wgt, k);
        int   jk = __shfl_sync(0xffffffffu, j, k);
        float2 hv = *((const float2*)(g_h + ((size_t)((b << 11) + jk) << 6)) + lane);
        z0 += wk * hv.x;
        z1 += wk * hv.y;
    }
    float rs = 1.f / s;
    z0 = fmaxf(z0 * rs, 0.f);
    z1 = fmaxf(z1 * rs, 0.f);
    float2 ev = *((const float2*)(emb + i * DD) + lane);
    float2 o = make_float2(z0 * ev.x, z1 * ev.y);
    *((float2*)(g_obuf + ((size_t)row << 6)) + lane) = o;
}

// ---------------------------------------------------------------------------
// 6) BN stats partial reduce (deterministic, float4)
__global__ __launch_bounds__(256) void red_kernel() {
    __shared__ float ss[1024], sq[1024];
    int t = threadIdx.x;
    int gt = blockIdx.x * 256 + t;
    const float4* p = (const float4*)g_obuf;
    float s[4] = {0.f, 0.f, 0.f, 0.f};
    float q[4] = {0.f, 0.f, 0.f, 0.f};
    const int total4 = ROWS * DD / 4;          // 1,048,576
    for (int idx = gt; idx < total4; idx += RED_BLOCKS * 256) {
        float4 v = p[idx];
        s[0] += v.x; q[0] += v.x * v.x;
        s[1] += v.y; q[1] += v.y * v.y;
        s[2] += v.z; q[2] += v.z * v.z;
        s[3] += v.w; q[3] += v.w * v.w;
    }
    #pragma unroll
    for (int jj = 0; jj < 4; jj++) { ss[t*4+jj] = s[jj]; sq[t*4+jj] = q[jj]; }
    __syncthreads();
    if (t < DD) {
        // slot s = 4*th + j holds channel s % 64; collect slots t + 64k
        float a = 0.f, b2 = 0.f;
        #pragma unroll
        for (int k = 0; k < 16; k++) {
            int slot = t + 64 * k;
            a  += ss[slot];
            b2 += sq[slot];
        }
        g_part[blockIdx.x * 128 + t]      = a;
        g_part[blockIdx.x * 128 + 64 + t] = b2;
    }
}

// 7) finalize mean / rsqrt(var+eps)
__global__ void stats_kernel() {
    int c = threadIdx.x;  // 64
    float s = 0.f, s2 = 0.f;
    for (int bk = 0; bk < RED_BLOCKS; bk++) {
        s  += g_part[bk * 128 + c];
        s2 += g_part[bk * 128 + 64 + c];
    }
    float mean = s / (float)ROWS;
    float var  = s2 / (float)ROWS - mean * mean;
    g_mean[c] = mean;
    g_inv[c]  = rsqrtf(var + 1e-5f);
}

// ---------------------------------------------------------------------------
// 8) BN apply + relu + fc  (warp per row, float2, channels 2l/2l+1)
__global__ __launch_bounds__(256) void out_kernel(
    const float* __restrict__ gamma, const float* __restrict__ beta,
    const float* __restrict__ fcw, const float* __restrict__ fcb,
    float* __restrict__ out) {
    int t = threadIdx.x, w = t >> 5, lane = t & 31;
    int row = blockIdx.x * 8 + w;
    float2 o  = *((const float2*)(g_obuf + ((size_t)row << 6)) + lane);
    float2 mn = *((const float2*)g_mean + lane);
    float2 iv = *((const float2*)g_inv + lane);
    float2 gm = *((const float2*)gamma + lane);
    float2 bt = *((const float2*)beta + lane);
    float2 fw = *((const float2*)fcw + lane);
    float v0 = fmaxf((o.x - mn.x) * iv.x * gm.x + bt.x, 0.f) * fw.x;
    float v1 = fmaxf((o.y - mn.y) * iv.y * gm.y + bt.y, 0.f) * fw.y;
    float acc = v0 + v1;
    #pragma unroll
    for (int off = 16; off; off >>= 1)
        acc += __shfl_down_sync(0xffffffffu, acc, off);
    if (lane == 0) out[row] = acc + fcb[0];
}

// ---------------------------------------------------------------------------
extern "C" void kernel_launch(void* const* d_in, const int* in_sizes, int n_in,
                              void* d_out, int out_size) {
    const float* x     = (const float*)d_in[0];
    const float* emb   = (const float*)d_in[1];
    const float* W     = (const float*)d_in[2];
    const float* Wb    = (const float*)d_in[3];
    const float* a_src = (const float*)d_in[4];
    const float* a_dst = (const float*)d_in[5];
    const float* gamma = (const float*)d_in[6];
    const float* beta  = (const float*)d_in[7];
    const float* fcw   = (const float*)d_in[8];
    const float* fcb   = (const float*)d_in[9];
    float* out = (float*)d_out;

    pre_kernel<<<NN/8, 256>>>(emb, W, Wb, a_src, a_dst);
    cos_kernel<<<dim3(NN/64, NN/64), dim3(16, 16)>>>(emb);
    topk_kernel<<<NN, 256>>>();
    h2_kernel<<<ROWS/32, 256>>>(x, W, Wb);
    agg_kernel<<<ROWS/8, 256>>>(emb);
    red_kernel<<<RED_BLOCKS, 256>>>();
    stats_kernel<<<1, 64>>>();
    out_kernel<<<ROWS/8, 256>>>(gamma, beta, fcw, fcb, out);
}